// round 3
// baseline (speedup 1.0000x reference)
#include <cuda_runtime.h>

// ---------------------------------------------------------------------------
// MixingBlock: s = softmax((x Wq)(sl Wk)^T * scale) @ sl,  w = the softmax
// Restructure: dots = x @ KQ^T with KQ = scale * (sl Wk) Wq^T  (tiny [128,180])
// ---------------------------------------------------------------------------

#define NB 4
#define NR 8192
#define NS 32
#define IN_DIM 180
#define SD 1536
#define AD 1536
#define BS (NB*NS)          // 128
#define KS 12
#define KCHUNK (SD/KS)      // 128

typedef unsigned long long ull;

__device__ float g_kpart[KS][BS][AD];
__device__ float g_KQT[IN_DIM][BS];     // KQ transposed (scale folded in)

// ---- packed f32x2 helpers -------------------------------------------------
__device__ __forceinline__ ull fpack(float x, float y) {
    ull r; asm("mov.b64 %0, {%1, %2};" : "=l"(r) : "f"(x), "f"(y)); return r;
}
__device__ __forceinline__ float2 funpack(ull v) {
    float2 r; asm("mov.b64 {%0, %1}, %2;" : "=f"(r.x), "=f"(r.y) : "l"(v)); return r;
}
__device__ __forceinline__ ull ffma2(ull a, ull b, ull c) {
    ull d; asm("fma.rn.f32x2 %0, %1, %2, %3;" : "=l"(d) : "l"(a), "l"(b), "l"(c)); return d;
}
__device__ __forceinline__ ull d2u(double d) { return __double_as_longlong(d); }
__device__ __forceinline__ double u2d(ull v) { return __longlong_as_double(v); }

// ---------------------------------------------------------------------------
// P1: g_kpart[p][m][n] = sum_{d in chunk p} sl[m][d] * Wk[d][n]
// grid (6 n-tiles, 2 m-tiles, 12 k-chunks), 256 thr.
// ---------------------------------------------------------------------------
__global__ __launch_bounds__(256, 2) void p1_kernel(const float* __restrict__ sl,
                                                    const float* __restrict__ Wk) {
    const int n0 = blockIdx.x * 256;
    const int m0 = blockIdx.y * 64;
    const int p  = blockIdx.z;
    const int d0 = p * KCHUNK;
    __shared__ float sWk[16][256];
    __shared__ ull   sslp[16][65];
    const int tid  = threadIdx.x;
    const int warp = tid >> 5, lane = tid & 31;
    const int mbase = warp * 8;

    ull acc[8][4];
    #pragma unroll
    for (int i = 0; i < 8; i++)
        #pragma unroll
        for (int q = 0; q < 4; q++) acc[i][q] = 0ULL;

    for (int kk = 0; kk < KCHUNK; kk += 16) {
        __syncthreads();
        #pragma unroll
        for (int t = 0; t < 4; t++) {
            int idx = t * 256 + tid;
            int dd = idx >> 6, nq = idx & 63;
            *(float4*)&sWk[dd][nq * 4] =
                *(const float4*)&Wk[(size_t)(d0 + kk + dd) * AD + n0 + nq * 4];
        }
        #pragma unroll
        for (int t = 0; t < 4; t++) {
            int idx = t * 256 + tid;
            int m = idx >> 4, dd = idx & 15;
            float v = sl[(size_t)(m0 + m) * SD + d0 + kk + dd];
            sslp[dd][m] = fpack(v, v);
        }
        __syncthreads();
        #pragma unroll
        for (int dd = 0; dd < 16; dd++) {
            double2 a01 = *(const double2*)&sWk[dd][lane * 4];
            double2 a23 = *(const double2*)&sWk[dd][128 + lane * 4];
            ull A0 = d2u(a01.x), A1 = d2u(a01.y), A2 = d2u(a23.x), A3 = d2u(a23.y);
            #pragma unroll
            for (int i = 0; i < 8; i++) {
                ull wv = sslp[dd][mbase + i];
                acc[i][0] = ffma2(A0, wv, acc[i][0]);
                acc[i][1] = ffma2(A1, wv, acc[i][1]);
                acc[i][2] = ffma2(A2, wv, acc[i][2]);
                acc[i][3] = ffma2(A3, wv, acc[i][3]);
            }
        }
    }
    #pragma unroll
    for (int i = 0; i < 8; i++) {
        int m = m0 + mbase + i;
        float* dst = &g_kpart[p][m][n0 + lane * 4];
        *(double2*)dst         = make_double2(u2d(acc[i][0]), u2d(acc[i][1]));
        *(double2*)(dst + 128) = make_double2(u2d(acc[i][2]), u2d(acc[i][3]));
    }
}

// ---------------------------------------------------------------------------
// P2: reduce partials, KQT[j][m] = scale * sum_a k[m][a]*Wq[j][a] (transposed!)
// ---------------------------------------------------------------------------
__global__ __launch_bounds__(256) void p2_kernel(const float* __restrict__ Wq) {
    const int r0 = blockIdx.x * 2;
    __shared__ float ksm[2][SD];
    const int tid = threadIdx.x;

    for (int idx = tid; idx < 2 * SD; idx += 256) {
        int row = idx / SD, a = idx - row * SD;
        float accv = 0.f;
        #pragma unroll
        for (int p = 0; p < KS; p++) accv += g_kpart[p][r0 + row][a];
        ksm[row][a] = accv;
    }
    __syncthreads();

    const int wid = tid >> 5, lane = tid & 31;
    const float scale = rsqrtf((float)AD);
    for (int o = wid; o < 2 * IN_DIM; o += 8) {
        int row = (o >= IN_DIM) ? 1 : 0;
        int j = o - row * IN_DIM;
        const float* wq = Wq + (size_t)j * AD;
        float4 a4 = make_float4(0.f, 0.f, 0.f, 0.f);
        for (int a = lane * 4; a < SD; a += 128) {
            float4 kv = *(const float4*)&ksm[row][a];
            float4 wv = *(const float4*)&wq[a];
            a4.x += kv.x * wv.x; a4.y += kv.y * wv.y;
            a4.z += kv.z * wv.z; a4.w += kv.w * wv.w;
        }
        float accv = (a4.x + a4.y) + (a4.z + a4.w);
        #pragma unroll
        for (int off = 16; off; off >>= 1)
            accv += __shfl_xor_sync(0xffffffffu, accv, off);
        if (lane == 0) g_KQT[j][r0 + row] = accv * scale;
    }
}

// ---------------------------------------------------------------------------
// C1: dots = x @ KQ^T (K=180), softmax over 32 slots, write w.
// grid 1024 (32 rows each), 128 thr. Thread: 2 rows x 4 slots.
// kqt fill is now fully coalesced thanks to g_KQT layout.
// ---------------------------------------------------------------------------
#define C1_ROWS 32
__global__ __launch_bounds__(128) void c1_kernel(const float* __restrict__ x,
                                                 float* __restrict__ w_out) {
    const int row0 = blockIdx.x * C1_ROWS;
    const int b = row0 >> 13;
    __shared__ float xs[C1_ROWS][IN_DIM];     // 23 KB
    __shared__ float kqt[IN_DIM][32];         // 23 KB, [j][s]
    const int tid = threadIdx.x;

    for (int idx = tid; idx < C1_ROWS * 45; idx += 128) {
        int r = idx / 45, q = idx - r * 45;
        *(float4*)&xs[r][q * 4] =
            *(const float4*)&x[(size_t)(row0 + r) * IN_DIM + q * 4];
    }
    for (int idx = tid; idx < IN_DIM * NS; idx += 128) {   // coalesced
        int j = idx >> 5, s = idx & 31;
        kqt[j][s] = g_KQT[j][b * NS + s];
    }
    __syncthreads();

    const int sg = tid & 7;     // slots sg*4 + {0..3}
    const int rp = tid >> 3;    // rows rp*2 + {0,1}
    ull acc[2][2] = {{0ULL, 0ULL}, {0ULL, 0ULL}};

    #pragma unroll 4
    for (int j = 0; j < IN_DIM; j++) {
        double2 kd = *(const double2*)&kqt[j][sg * 4];
        ull k0 = d2u(kd.x), k1 = d2u(kd.y);
        #pragma unroll
        for (int i = 0; i < 2; i++) {
            float xv = xs[rp * 2 + i][j];
            ull xd = fpack(xv, xv);
            acc[i][0] = ffma2(k0, xd, acc[i][0]);
            acc[i][1] = ffma2(k1, xd, acc[i][1]);
        }
    }
    #pragma unroll
    for (int i = 0; i < 2; i++) {
        float2 d01 = funpack(acc[i][0]), d23 = funpack(acc[i][1]);
        float m = fmaxf(fmaxf(d01.x, d01.y), fmaxf(d23.x, d23.y));
        m = fmaxf(m, __shfl_xor_sync(0xffffffffu, m, 1));
        m = fmaxf(m, __shfl_xor_sync(0xffffffffu, m, 2));
        m = fmaxf(m, __shfl_xor_sync(0xffffffffu, m, 4));
        float e0 = __expf(d01.x - m), e1 = __expf(d01.y - m);
        float e2 = __expf(d23.x - m), e3 = __expf(d23.y - m);
        float sum = (e0 + e1) + (e2 + e3);
        sum += __shfl_xor_sync(0xffffffffu, sum, 1);
        sum += __shfl_xor_sync(0xffffffffu, sum, 2);
        sum += __shfl_xor_sync(0xffffffffu, sum, 4);
        float inv = 1.0f / sum;
        int r = row0 + rp * 2 + i;
        *(float4*)&w_out[(size_t)r * NS + sg * 4] =
            make_float4(e0 * inv, e1 * inv, e2 * inv, e3 * inv);
    }
}

// ---------------------------------------------------------------------------
// C2: s_out[r][d] = sum_s w[r][s] * sl[b][s][d]   (K=32 skinny GEMM)
// grid (6 d-tiles x 1024 row-tiles), 128 thr. Block tile 32 rows x 256 d.
// Warp = 8 rows x 256 d; w splats loaded as PAIRS (LDS.128 broadcast = 2 s).
// ---------------------------------------------------------------------------
__global__ __launch_bounds__(128, 4) void c2_kernel(const float* __restrict__ sl,
                                                    const float* __restrict__ w_in,
                                                    float* __restrict__ s_out) {
    const int d0   = blockIdx.x * 256;
    const int row0 = blockIdx.y * 32;
    const int b    = row0 >> 13;
    __shared__ float sls[NS][256];    // 32 KB
    __shared__ ull   wsp[32][NS];     // splatted w, 8 KB
    const int tid  = threadIdx.x;
    const int warp = tid >> 5, lane = tid & 31;
    const int rbase = warp * 8;

    #pragma unroll
    for (int t = 0; t < 16; t++) {
        int idx = t * 128 + tid;
        int s = idx >> 6, dq = idx & 63;
        *(float4*)&sls[s][dq * 4] =
            *(const float4*)&sl[(size_t)(b * NS + s) * SD + d0 + dq * 4];
    }
    #pragma unroll
    for (int t = 0; t < 8; t++) {
        int idx = t * 128 + tid;
        int r = idx >> 5, s = idx & 31;
        float v = w_in[(size_t)(row0 + r) * NS + s];
        wsp[r][s] = fpack(v, v);
    }
    __syncthreads();

    ull acc[8][4];
    #pragma unroll
    for (int i = 0; i < 8; i++)
        #pragma unroll
        for (int q = 0; q < 4; q++) acc[i][q] = 0ULL;

    #pragma unroll 2
    for (int s = 0; s < NS; s += 2) {
        double2 a01 = *(const double2*)&sls[s][lane * 4];
        double2 a23 = *(const double2*)&sls[s][128 + lane * 4];
        double2 b01 = *(const double2*)&sls[s + 1][lane * 4];
        double2 b23 = *(const double2*)&sls[s + 1][128 + lane * 4];
        ull A0 = d2u(a01.x), A1 = d2u(a01.y), A2 = d2u(a23.x), A3 = d2u(a23.y);
        ull B0 = d2u(b01.x), B1 = d2u(b01.y), B2 = d2u(b23.x), B3 = d2u(b23.y);
        #pragma unroll
        for (int i = 0; i < 8; i++) {
            double2 wp = *(const double2*)&wsp[rbase + i][s];  // splat pair (s, s+1)
            ull w0 = d2u(wp.x), w1 = d2u(wp.y);
            acc[i][0] = ffma2(A0, w0, acc[i][0]);
            acc[i][1] = ffma2(A1, w0, acc[i][1]);
            acc[i][2] = ffma2(A2, w0, acc[i][2]);
            acc[i][3] = ffma2(A3, w0, acc[i][3]);
            acc[i][0] = ffma2(B0, w1, acc[i][0]);
            acc[i][1] = ffma2(B1, w1, acc[i][1]);
            acc[i][2] = ffma2(B2, w1, acc[i][2]);
            acc[i][3] = ffma2(B3, w1, acc[i][3]);
        }
    }
    #pragma unroll
    for (int i = 0; i < 8; i++) {
        int r = row0 + rbase + i;
        float* dst = s_out + (size_t)r * SD + d0 + lane * 4;
        *(double2*)dst         = make_double2(u2d(acc[i][0]), u2d(acc[i][1]));
        *(double2*)(dst + 128) = make_double2(u2d(acc[i][2]), u2d(acc[i][3]));
    }
}

// ---------------------------------------------------------------------------
extern "C" void kernel_launch(void* const* d_in, const int* in_sizes, int n_in,
                              void* d_out, int out_size) {
    const float* x  = (const float*)d_in[0];   // [4,8192,180]
    const float* sl = (const float*)d_in[1];   // [4,32,1536]
    const float* Wq = (const float*)d_in[2];   // [180,1536]
    const float* Wk = (const float*)d_in[3];   // [1536,1536]
    float* out   = (float*)d_out;
    float* s_out = out;                               // [4,8192,1536]
    float* w_out = out + (size_t)NB * NR * SD;        // [4,8192,32]

    p1_kernel<<<dim3(AD / 256, BS / 64, KS), 256>>>(sl, Wk);
    p2_kernel<<<BS / 2, 256>>>(Wq);
    c1_kernel<<<(NB * NR) / C1_ROWS, 128>>>(x, w_out);
    c2_kernel<<<dim3(SD / 256, (NB * NR) / 32), 128>>>(sl, w_out, s_out);
}

// round 5
// speedup vs baseline: 1.0610x; 1.0610x over previous
#include <cuda_runtime.h>

// ---------------------------------------------------------------------------
// MixingBlock: s = softmax((x Wq)(sl Wk)^T * scale) @ sl,  w = the softmax
// Restructure: dots = x @ KQ^T with KQ = scale * (sl Wk) Wq^T  (tiny [128,180])
// ---------------------------------------------------------------------------

#define NB 4
#define NR 8192
#define NS 32
#define IN_DIM 180
#define SD 1536
#define AD 1536
#define BS (NB*NS)          // 128
#define KS 12
#define KCHUNK (SD/KS)      // 128
#define AC 6                // a-chunks for p2
#define ACHUNK (AD/AC)      // 256

typedef unsigned long long ull;

__device__ float g_kpart[KS][BS][AD];
__device__ float g_KQp[AC][IN_DIM][BS];   // p2 partials
__device__ float g_KQT[IN_DIM][BS];       // KQ transposed (scale folded in)

// ---- packed f32x2 helpers -------------------------------------------------
__device__ __forceinline__ ull fpack(float x, float y) {
    ull r; asm("mov.b64 %0, {%1, %2};" : "=l"(r) : "f"(x), "f"(y)); return r;
}
__device__ __forceinline__ float2 funpack(ull v) {
    float2 r; asm("mov.b64 {%0, %1}, %2;" : "=f"(r.x), "=f"(r.y) : "l"(v)); return r;
}
__device__ __forceinline__ ull ffma2(ull a, ull b, ull c) {
    ull d; asm("fma.rn.f32x2 %0, %1, %2, %3;" : "=l"(d) : "l"(a), "l"(b), "l"(c)); return d;
}
__device__ __forceinline__ ull d2u(double d) { return __double_as_longlong(d); }
__device__ __forceinline__ double u2d(ull v) { return __longlong_as_double(v); }

// ---------------------------------------------------------------------------
// P1: g_kpart[p][m][n] = sum_{d in chunk p} sl[m][d] * Wk[d][n]
// grid (6, 2, 12), 256 thr.
// ---------------------------------------------------------------------------
__global__ __launch_bounds__(256, 2) void p1_kernel(const float* __restrict__ sl,
                                                    const float* __restrict__ Wk) {
    const int n0 = blockIdx.x * 256;
    const int m0 = blockIdx.y * 64;
    const int p  = blockIdx.z;
    const int d0 = p * KCHUNK;
    __shared__ float sWk[16][256];
    __shared__ ull   sslp[16][65];
    const int tid  = threadIdx.x;
    const int warp = tid >> 5, lane = tid & 31;
    const int mbase = warp * 8;

    ull acc[8][4];
    #pragma unroll
    for (int i = 0; i < 8; i++)
        #pragma unroll
        for (int q = 0; q < 4; q++) acc[i][q] = 0ULL;

    for (int kk = 0; kk < KCHUNK; kk += 16) {
        __syncthreads();
        #pragma unroll
        for (int t = 0; t < 4; t++) {
            int idx = t * 256 + tid;
            int dd = idx >> 6, nq = idx & 63;
            *(float4*)&sWk[dd][nq * 4] =
                *(const float4*)&Wk[(size_t)(d0 + kk + dd) * AD + n0 + nq * 4];
        }
        #pragma unroll
        for (int t = 0; t < 4; t++) {
            int idx = t * 256 + tid;
            int m = idx >> 4, dd = idx & 15;
            float v = sl[(size_t)(m0 + m) * SD + d0 + kk + dd];
            sslp[dd][m] = fpack(v, v);
        }
        __syncthreads();
        #pragma unroll
        for (int dd = 0; dd < 16; dd++) {
            double2 a01 = *(const double2*)&sWk[dd][lane * 4];
            double2 a23 = *(const double2*)&sWk[dd][128 + lane * 4];
            ull A0 = d2u(a01.x), A1 = d2u(a01.y), A2 = d2u(a23.x), A3 = d2u(a23.y);
            #pragma unroll
            for (int i = 0; i < 8; i++) {
                ull wv = sslp[dd][mbase + i];
                acc[i][0] = ffma2(A0, wv, acc[i][0]);
                acc[i][1] = ffma2(A1, wv, acc[i][1]);
                acc[i][2] = ffma2(A2, wv, acc[i][2]);
                acc[i][3] = ffma2(A3, wv, acc[i][3]);
            }
        }
    }
    #pragma unroll
    for (int i = 0; i < 8; i++) {
        int m = m0 + mbase + i;
        float* dst = &g_kpart[p][m][n0 + lane * 4];
        *(double2*)dst         = make_double2(u2d(acc[i][0]), u2d(acc[i][1]));
        *(double2*)(dst + 128) = make_double2(u2d(acc[i][2]), u2d(acc[i][3]));
    }
}

// ---------------------------------------------------------------------------
// P2: k-split GEMM.  g_KQp[ac][j][m] = scale * sum_{a in chunk} k[m][a]*Wq[j][a]
// grid (8 m-tiles of 16, 6 a-chunks of 256), 256 thr (8 warps).
// ---------------------------------------------------------------------------
__global__ __launch_bounds__(256) void p2_kernel(const float* __restrict__ Wq) {
    const int m0 = blockIdx.x * 16;
    const int ac = blockIdx.y;
    const int a0 = ac * ACHUNK;
    __shared__ float ks[16][260];       // reduced k tile
    const int tid = threadIdx.x;
    const int wid = tid >> 5, lane = tid & 31;

    // reduce 12 kpart partials into ks: 16 m x 64 float4 = 1024 loads = 4 iters
    #pragma unroll
    for (int t = 0; t < 4; t++) {
        int idx = t * 256 + tid;
        int m = idx >> 6, aq = idx & 63;
        float4 acc4 = make_float4(0.f, 0.f, 0.f, 0.f);
        #pragma unroll
        for (int p = 0; p < KS; p++) {
            float4 v = *(const float4*)&g_kpart[p][m0 + m][a0 + aq * 4];
            acc4.x += v.x; acc4.y += v.y; acc4.z += v.z; acc4.w += v.w;
        }
        *(float4*)&ks[m][aq * 4] = acc4;
    }
    __syncthreads();

    const float scale = rsqrtf((float)AD);
    for (int j = wid; j < IN_DIM; j += 8) {
        const float* wq = Wq + (size_t)j * AD + a0;
        float4 w0 = *(const float4*)&wq[lane * 4];
        float4 w1 = *(const float4*)&wq[128 + lane * 4];
        #pragma unroll 4
        for (int m = 0; m < 16; m++) {
            float4 k0 = *(const float4*)&ks[m][lane * 4];
            float4 k1 = *(const float4*)&ks[m][128 + lane * 4];
            float v = w0.x * k0.x + w0.y * k0.y + w0.z * k0.z + w0.w * k0.w
                    + w1.x * k1.x + w1.y * k1.y + w1.z * k1.z + w1.w * k1.w;
            #pragma unroll
            for (int off = 16; off; off >>= 1)
                v += __shfl_xor_sync(0xffffffffu, v, off);
            if (lane == 0) g_KQp[ac][j][m0 + m] = v * scale;
        }
    }
}

// ---------------------------------------------------------------------------
// P2R: g_KQT[j][m] = sum_ac g_KQp[ac][j][m]
// ---------------------------------------------------------------------------
__global__ __launch_bounds__(256) void p2r_kernel() {
    int idx = blockIdx.x * 256 + threadIdx.x;   // over 180*128
    float acc = 0.f;
    #pragma unroll
    for (int c = 0; c < AC; c++) acc += (&g_KQp[c][0][0])[idx];
    (&g_KQT[0][0])[idx] = acc;
}

// ---------------------------------------------------------------------------
// C1: dots = x @ KQ^T (K=180), softmax over 32 slots, write w.
// grid 1024 (32 rows each), 128 thr. Thread: 2 rows x 4 slots.
// ---------------------------------------------------------------------------
#define C1_ROWS 32
__global__ __launch_bounds__(128) void c1_kernel(const float* __restrict__ x,
                                                 float* __restrict__ w_out) {
    const int row0 = blockIdx.x * C1_ROWS;
    const int b = row0 >> 13;
    __shared__ float xs[C1_ROWS][IN_DIM];
    __shared__ float kqt[IN_DIM][32];
    const int tid = threadIdx.x;

    for (int idx = tid; idx < C1_ROWS * 45; idx += 128) {
        int r = idx / 45, q = idx - r * 45;
        *(float4*)&xs[r][q * 4] =
            *(const float4*)&x[(size_t)(row0 + r) * IN_DIM + q * 4];
    }
    for (int idx = tid; idx < IN_DIM * NS; idx += 128) {
        int j = idx >> 5, s = idx & 31;
        kqt[j][s] = g_KQT[j][b * NS + s];
    }
    __syncthreads();

    const int sg = tid & 7;
    const int rp = tid >> 3;
    ull acc[2][2] = {{0ULL, 0ULL}, {0ULL, 0ULL}};

    #pragma unroll 4
    for (int j = 0; j < IN_DIM; j++) {
        double2 kd = *(const double2*)&kqt[j][sg * 4];
        ull k0 = d2u(kd.x), k1 = d2u(kd.y);
        #pragma unroll
        for (int i = 0; i < 2; i++) {
            float xv = xs[rp * 2 + i][j];
            ull xd = fpack(xv, xv);
            acc[i][0] = ffma2(k0, xd, acc[i][0]);
            acc[i][1] = ffma2(k1, xd, acc[i][1]);
        }
    }
    #pragma unroll
    for (int i = 0; i < 2; i++) {
        float2 d01 = funpack(acc[i][0]), d23 = funpack(acc[i][1]);
        float m = fmaxf(fmaxf(d01.x, d01.y), fmaxf(d23.x, d23.y));
        m = fmaxf(m, __shfl_xor_sync(0xffffffffu, m, 1));
        m = fmaxf(m, __shfl_xor_sync(0xffffffffu, m, 2));
        m = fmaxf(m, __shfl_xor_sync(0xffffffffu, m, 4));
        float e0 = __expf(d01.x - m), e1 = __expf(d01.y - m);
        float e2 = __expf(d23.x - m), e3 = __expf(d23.y - m);
        float sum = (e0 + e1) + (e2 + e3);
        sum += __shfl_xor_sync(0xffffffffu, sum, 1);
        sum += __shfl_xor_sync(0xffffffffu, sum, 2);
        sum += __shfl_xor_sync(0xffffffffu, sum, 4);
        float inv = 1.0f / sum;
        int r = row0 + rp * 2 + i;
        *(float4*)&w_out[(size_t)r * NS + sg * 4] =
            make_float4(e0 * inv, e1 * inv, e2 * inv, e3 * inv);
    }
}

// ---------------------------------------------------------------------------
// C2: s_out[r][d] = sum_s w[r][s] * sl[b][s][d]   (K=32 skinny GEMM)
// grid (12 d-tiles x 512 row-tiles), 128 thr. Block tile 64 rows x 128 d.
// Warp = 16 rows x 128 d; lane owns one float4; w splats read as pairs.
// ---------------------------------------------------------------------------
__global__ __launch_bounds__(128, 5) void c2_kernel(const float* __restrict__ sl,
                                                    const float* __restrict__ w_in,
                                                    float* __restrict__ s_out) {
    const int d0   = blockIdx.x * 128;
    const int row0 = blockIdx.y * 64;
    const int b    = row0 >> 13;
    __shared__ float sls[NS][128];    // 16 KB
    __shared__ ull   wsp[64][NS];     // 16 KB splatted w
    const int tid  = threadIdx.x;
    const int warp = tid >> 5, lane = tid & 31;
    const int rbase = warp * 16;

    #pragma unroll
    for (int t = 0; t < 8; t++) {     // 32 s x 128 d (float4)
        int idx = t * 128 + tid;
        int s = idx >> 5, dq = idx & 31;
        *(float4*)&sls[s][dq * 4] =
            *(const float4*)&sl[(size_t)(b * NS + s) * SD + d0 + dq * 4];
    }
    #pragma unroll
    for (int t = 0; t < 16; t++) {    // 64 rows x 32 s, splatted
        int idx = t * 128 + tid;
        int r = idx >> 5, s = idx & 31;
        float v = w_in[(size_t)(row0 + r) * NS + s];
        wsp[r][s] = fpack(v, v);
    }
    __syncthreads();

    ull acc[16][2];
    #pragma unroll
    for (int i = 0; i < 16; i++) { acc[i][0] = 0ULL; acc[i][1] = 0ULL; }

    #pragma unroll 2
    for (int s = 0; s < NS; s += 2) {
        double2 av = *(const double2*)&sls[s][lane * 4];
        double2 bv = *(const double2*)&sls[s + 1][lane * 4];
        ull A0 = d2u(av.x), A1 = d2u(av.y);
        ull B0 = d2u(bv.x), B1 = d2u(bv.y);
        #pragma unroll
        for (int i = 0; i < 16; i++) {
            double2 wp = *(const double2*)&wsp[rbase + i][s];   // splats (s, s+1)
            ull w0 = d2u(wp.x), w1 = d2u(wp.y);
            acc[i][0] = ffma2(A0, w0, acc[i][0]);
            acc[i][1] = ffma2(A1, w0, acc[i][1]);
            acc[i][0] = ffma2(B0, w1, acc[i][0]);
            acc[i][1] = ffma2(B1, w1, acc[i][1]);
        }
    }
    #pragma unroll
    for (int i = 0; i < 16; i++) {
        int r = row0 + rbase + i;
        float* dst = s_out + (size_t)r * SD + d0 + lane * 4;
        *(double2*)dst = make_double2(u2d(acc[i][0]), u2d(acc[i][1]));
    }
}

// ---------------------------------------------------------------------------
extern "C" void kernel_launch(void* const* d_in, const int* in_sizes, int n_in,
                              void* d_out, int out_size) {
    const float* x  = (const float*)d_in[0];   // [4,8192,180]
    const float* sl = (const float*)d_in[1];   // [4,32,1536]
    const float* Wq = (const float*)d_in[2];   // [180,1536]
    const float* Wk = (const float*)d_in[3];   // [1536,1536]
    float* out   = (float*)d_out;
    float* s_out = out;                               // [4,8192,1536]
    float* w_out = out + (size_t)NB * NR * SD;        // [4,8192,32]

    p1_kernel<<<dim3(AD / 256, BS / 64, KS), 256>>>(sl, Wk);
    p2_kernel<<<dim3(BS / 16, AC), 256>>>(Wq);
    p2r_kernel<<<(IN_DIM * BS) / 256, 256>>>();
    c1_kernel<<<(NB * NR) / C1_ROWS, 128>>>(x, w_out);
    c2_kernel<<<dim3(SD / 128, (NB * NR) / 64), 128>>>(sl, w_out, s_out);
}

// round 6
// speedup vs baseline: 1.3165x; 1.2408x over previous
#include <cuda_runtime.h>

// ---------------------------------------------------------------------------
// MixingBlock: s = softmax((x Wq)(sl Wk)^T * scale) @ sl,  w = the softmax
// Restructure: dots = x @ KQ^T with KQ = scale * (sl Wk) Wq^T  (tiny [128,180])
// ---------------------------------------------------------------------------

#define NB 4
#define NR 8192
#define NS 32
#define IN_DIM 180
#define SD 1536
#define AD 1536
#define BS (NB*NS)          // 128
#define KS 24               // d-split for p1
#define KCHUNK (SD/KS)      // 64
#define AC 24               // a-chunks for p2
#define ACHUNK (AD/AC)      // 64
#define JT 16               // j-tile for p2 (12 tiles, padded to 192)

typedef unsigned long long ull;

__device__ float g_kpart[KS][BS][AD];     // p1 partials (18.9 MB)
__device__ float g_kred[BS][AD];          // reduced k
__device__ float g_KQp[AC][192][BS];      // p2 partials
__device__ float g_KQT[IN_DIM][BS];       // KQ transposed (scale folded in)

// ---- packed f32x2 helpers -------------------------------------------------
__device__ __forceinline__ ull fpack(float x, float y) {
    ull r; asm("mov.b64 %0, {%1, %2};" : "=l"(r) : "f"(x), "f"(y)); return r;
}
__device__ __forceinline__ float2 funpack(ull v) {
    float2 r; asm("mov.b64 {%0, %1}, %2;" : "=f"(r.x), "=f"(r.y) : "l"(v)); return r;
}
__device__ __forceinline__ ull ffma2(ull a, ull b, ull c) {
    ull d; asm("fma.rn.f32x2 %0, %1, %2, %3;" : "=l"(d) : "l"(a), "l"(b), "l"(c)); return d;
}
__device__ __forceinline__ ull d2u(double d) { return __double_as_longlong(d); }
__device__ __forceinline__ double u2d(ull v) { return __longlong_as_double(v); }

// ---------------------------------------------------------------------------
// P1: g_kpart[p][m][n] = sum_{d in chunk p} sl[m][d] * Wk[d][n]
// grid (6 n-tiles of 256, 4 m-tiles of 32, 24 d-chunks of 64), 128 thr.
// Warp = 8m x 256n (lane owns 2 distinct float4) -> balanced fma/crossbar.
// ---------------------------------------------------------------------------
__global__ __launch_bounds__(128) void p1_kernel(const float* __restrict__ sl,
                                                 const float* __restrict__ Wk) {
    const int n0 = blockIdx.x * 256;
    const int m0 = blockIdx.y * 32;
    const int p  = blockIdx.z;
    const int d0 = p * KCHUNK;
    __shared__ float sWk[16][256];   // 16 KB
    __shared__ ull   sslp[16][33];   // splatted sl, padded
    const int tid  = threadIdx.x;
    const int warp = tid >> 5, lane = tid & 31;
    const int mbase = warp * 8;

    ull acc[8][4];
    #pragma unroll
    for (int i = 0; i < 8; i++)
        #pragma unroll
        for (int q = 0; q < 4; q++) acc[i][q] = 0ULL;

    for (int kk = 0; kk < KCHUNK; kk += 16) {
        __syncthreads();
        #pragma unroll
        for (int t = 0; t < 8; t++) {            // Wk tile 16 x 256 (float4)
            int idx = t * 128 + tid;
            int dd = idx >> 6, nq = idx & 63;
            *(float4*)&sWk[dd][nq * 4] =
                *(const float4*)&Wk[(size_t)(d0 + kk + dd) * AD + n0 + nq * 4];
        }
        #pragma unroll
        for (int t = 0; t < 4; t++) {            // sl tile 32m x 16d, splatted
            int idx = t * 128 + tid;
            int m = idx >> 4, dd = idx & 15;
            float v = sl[(size_t)(m0 + m) * SD + d0 + kk + dd];
            sslp[dd][m] = fpack(v, v);
        }
        __syncthreads();
        #pragma unroll
        for (int dd = 0; dd < 16; dd++) {
            double2 a01 = *(const double2*)&sWk[dd][lane * 4];
            double2 a23 = *(const double2*)&sWk[dd][128 + lane * 4];
            ull A0 = d2u(a01.x), A1 = d2u(a01.y), A2 = d2u(a23.x), A3 = d2u(a23.y);
            #pragma unroll
            for (int i = 0; i < 8; i++) {
                ull wv = sslp[dd][mbase + i];
                acc[i][0] = ffma2(A0, wv, acc[i][0]);
                acc[i][1] = ffma2(A1, wv, acc[i][1]);
                acc[i][2] = ffma2(A2, wv, acc[i][2]);
                acc[i][3] = ffma2(A3, wv, acc[i][3]);
            }
        }
    }
    #pragma unroll
    for (int i = 0; i < 8; i++) {
        int m = m0 + mbase + i;
        float* dst = &g_kpart[p][m][n0 + lane * 4];
        *(double2*)dst         = make_double2(u2d(acc[i][0]), u2d(acc[i][1]));
        *(double2*)(dst + 128) = make_double2(u2d(acc[i][2]), u2d(acc[i][3]));
    }
}

// ---------------------------------------------------------------------------
// P1R: g_kred = sum_p g_kpart[p]   (float4 grid-stride, 192 blocks)
// ---------------------------------------------------------------------------
__global__ __launch_bounds__(256) void p1r_kernel() {
    int gid = blockIdx.x * 256 + threadIdx.x;    // over 128*1536/4 = 49152
    const float4* src = (const float4*)&g_kpart[0][0][0];
    float4* dst = (float4*)&g_kred[0][0];
    const int stride = (BS * AD) / 4;
    float4 a = make_float4(0.f, 0.f, 0.f, 0.f);
    #pragma unroll
    for (int p = 0; p < KS; p++) {
        float4 v = src[(size_t)p * stride + gid];
        a.x += v.x; a.y += v.y; a.z += v.z; a.w += v.w;
    }
    dst[gid] = a;
}

// ---------------------------------------------------------------------------
// P2: KQp[ac][j][m] = scale * sum_{a in chunk} kred[m][a] * Wq[j][a]
// grid (12 j-tiles of 16, 24 a-chunks of 64), 256 thr.
// Thread = m-pair x 4 j, f32x2. No shfl.
// ---------------------------------------------------------------------------
__global__ __launch_bounds__(256) void p2_kernel(const float* __restrict__ Wq) {
    const int j0 = blockIdx.x * JT;
    const int ac = blockIdx.y;
    const int a0 = ac * ACHUNK;
    __shared__ float ksm[64][130];    // [a][m], padded (33.3 KB)
    __shared__ ull   wqs[64][18];     // splatted Wq [a][jj], padded (9.2 KB)
    const int tid = threadIdx.x;
    const int mp = tid & 63;          // m-pair: m = 2*mp
    const int jg = tid >> 6;          // j = j0 + jg*4 + {0..3}

    // fill ksm (transpose): 128 m x 16 float4 = 2048 -> 8 iters
    #pragma unroll
    for (int t = 0; t < 8; t++) {
        int idx = t * 256 + tid;
        int m = idx >> 4, aq = idx & 15;
        float4 v = *(const float4*)&g_kred[m][a0 + aq * 4];
        ksm[aq * 4 + 0][m] = v.x;
        ksm[aq * 4 + 1][m] = v.y;
        ksm[aq * 4 + 2][m] = v.z;
        ksm[aq * 4 + 3][m] = v.w;
    }
    // fill wqs splats: 16 jj x 64 a = 1024 -> 4 iters
    const float scale = rsqrtf((float)AD);
    #pragma unroll
    for (int t = 0; t < 4; t++) {
        int idx = t * 256 + tid;
        int jj = idx >> 6, a = idx & 63;
        int j = j0 + jj;
        float v = (j < IN_DIM) ? Wq[(size_t)j * AD + a0 + a] * scale : 0.f;
        wqs[a][jj] = fpack(v, v);
    }
    __syncthreads();

    ull acc[4] = {0ULL, 0ULL, 0ULL, 0ULL};
    #pragma unroll 4
    for (int a = 0; a < ACHUNK; a++) {
        ull kp = *(const ull*)&ksm[a][2 * mp];
        double2 w01 = *(const double2*)&wqs[a][jg * 4];
        double2 w23 = *(const double2*)&wqs[a][jg * 4 + 2];
        acc[0] = ffma2(kp, d2u(w01.x), acc[0]);
        acc[1] = ffma2(kp, d2u(w01.y), acc[1]);
        acc[2] = ffma2(kp, d2u(w23.x), acc[2]);
        acc[3] = ffma2(kp, d2u(w23.y), acc[3]);
    }
    #pragma unroll
    for (int q = 0; q < 4; q++) {
        int j = j0 + jg * 4 + q;
        if (j < IN_DIM) {
            float2 v = funpack(acc[q]);
            *(float2*)&g_KQp[ac][j][2 * mp] = v;
        }
    }
}

// ---------------------------------------------------------------------------
// P2R: g_KQT[j][m] = sum_ac g_KQp[ac][j][m]   (90 blocks)
// ---------------------------------------------------------------------------
__global__ __launch_bounds__(256) void p2r_kernel() {
    int idx = blockIdx.x * 256 + threadIdx.x;    // over 180*128
    int j = idx >> 7, m = idx & 127;
    float acc = 0.f;
    #pragma unroll
    for (int c = 0; c < AC; c++) acc += g_KQp[c][j][m];
    g_KQT[j][m] = acc;
}

// ---------------------------------------------------------------------------
// C1: dots = x @ KQ^T (K=180), softmax over 32 slots, write w.
// grid 1024 (32 rows), 256 thr. Thread = 1 row x 4 slots. occ ~50%.
// ---------------------------------------------------------------------------
#define C1_ROWS 32
__global__ __launch_bounds__(256) void c1_kernel(const float* __restrict__ x,
                                                 float* __restrict__ w_out) {
    const int row0 = blockIdx.x * C1_ROWS;
    const int b = row0 >> 13;
    __shared__ float xs[C1_ROWS][IN_DIM];     // 23 KB
    __shared__ float kqt[IN_DIM][32];         // 23 KB
    const int tid = threadIdx.x;

    for (int idx = tid; idx < C1_ROWS * 45; idx += 256) {
        int r = idx / 45, q = idx - r * 45;
        *(float4*)&xs[r][q * 4] =
            *(const float4*)&x[(size_t)(row0 + r) * IN_DIM + q * 4];
    }
    for (int idx = tid; idx < IN_DIM * NS; idx += 256) {
        int j = idx >> 5, s = idx & 31;
        kqt[j][s] = g_KQT[j][b * NS + s];
    }
    __syncthreads();

    const int sg = tid & 7;     // slots sg*4 + {0..3}
    const int r  = tid >> 3;    // row (0..31)
    ull acc0 = 0ULL, acc1 = 0ULL;

    #pragma unroll 6
    for (int j = 0; j < IN_DIM; j++) {
        double2 kd = *(const double2*)&kqt[j][sg * 4];
        float xv = xs[r][j];
        ull xd = fpack(xv, xv);
        acc0 = ffma2(d2u(kd.x), xd, acc0);
        acc1 = ffma2(d2u(kd.y), xd, acc1);
    }
    float2 d01 = funpack(acc0), d23 = funpack(acc1);
    float m = fmaxf(fmaxf(d01.x, d01.y), fmaxf(d23.x, d23.y));
    m = fmaxf(m, __shfl_xor_sync(0xffffffffu, m, 1));
    m = fmaxf(m, __shfl_xor_sync(0xffffffffu, m, 2));
    m = fmaxf(m, __shfl_xor_sync(0xffffffffu, m, 4));
    float e0 = __expf(d01.x - m), e1 = __expf(d01.y - m);
    float e2 = __expf(d23.x - m), e3 = __expf(d23.y - m);
    float sum = (e0 + e1) + (e2 + e3);
    sum += __shfl_xor_sync(0xffffffffu, sum, 1);
    sum += __shfl_xor_sync(0xffffffffu, sum, 2);
    sum += __shfl_xor_sync(0xffffffffu, sum, 4);
    float inv = 1.0f / sum;
    *(float4*)&w_out[(size_t)(row0 + r) * NS + sg * 4] =
        make_float4(e0 * inv, e1 * inv, e2 * inv, e3 * inv);
}

// ---------------------------------------------------------------------------
// C2: s_out[r][d] = sum_s w[r][s] * sl[b][s][d]   (K=32 skinny GEMM)
// grid (12 d-tiles x 512 row-tiles), 128 thr. Warp = 16 rows x 128 d.
// At the f32x2 issue floor — unchanged.
// ---------------------------------------------------------------------------
__global__ __launch_bounds__(128, 5) void c2_kernel(const float* __restrict__ sl,
                                                    const float* __restrict__ w_in,
                                                    float* __restrict__ s_out) {
    const int d0   = blockIdx.x * 128;
    const int row0 = blockIdx.y * 64;
    const int b    = row0 >> 13;
    __shared__ float sls[NS][128];    // 16 KB
    __shared__ ull   wsp[64][NS];     // 16 KB splatted w
    const int tid  = threadIdx.x;
    const int warp = tid >> 5, lane = tid & 31;
    const int rbase = warp * 16;

    #pragma unroll
    for (int t = 0; t < 8; t++) {
        int idx = t * 128 + tid;
        int s = idx >> 5, dq = idx & 31;
        *(float4*)&sls[s][dq * 4] =
            *(const float4*)&sl[(size_t)(b * NS + s) * SD + d0 + dq * 4];
    }
    #pragma unroll
    for (int t = 0; t < 16; t++) {
        int idx = t * 128 + tid;
        int r = idx >> 5, s = idx & 31;
        float v = w_in[(size_t)(row0 + r) * NS + s];
        wsp[r][s] = fpack(v, v);
    }
    __syncthreads();

    ull acc[16][2];
    #pragma unroll
    for (int i = 0; i < 16; i++) { acc[i][0] = 0ULL; acc[i][1] = 0ULL; }

    #pragma unroll 2
    for (int s = 0; s < NS; s += 2) {
        double2 av = *(const double2*)&sls[s][lane * 4];
        double2 bv = *(const double2*)&sls[s + 1][lane * 4];
        ull A0 = d2u(av.x), A1 = d2u(av.y);
        ull B0 = d2u(bv.x), B1 = d2u(bv.y);
        #pragma unroll
        for (int i = 0; i < 16; i++) {
            double2 wp = *(const double2*)&wsp[rbase + i][s];
            ull w0 = d2u(wp.x), w1 = d2u(wp.y);
            acc[i][0] = ffma2(A0, w0, acc[i][0]);
            acc[i][1] = ffma2(A1, w0, acc[i][1]);
            acc[i][0] = ffma2(B0, w1, acc[i][0]);
            acc[i][1] = ffma2(B1, w1, acc[i][1]);
        }
    }
    #pragma unroll
    for (int i = 0; i < 16; i++) {
        int r = row0 + rbase + i;
        float* dst = s_out + (size_t)r * SD + d0 + lane * 4;
        *(double2*)dst = make_double2(u2d(acc[i][0]), u2d(acc[i][1]));
    }
}

// ---------------------------------------------------------------------------
extern "C" void kernel_launch(void* const* d_in, const int* in_sizes, int n_in,
                              void* d_out, int out_size) {
    const float* x  = (const float*)d_in[0];   // [4,8192,180]
    const float* sl = (const float*)d_in[1];   // [4,32,1536]
    const float* Wq = (const float*)d_in[2];   // [180,1536]
    const float* Wk = (const float*)d_in[3];   // [1536,1536]
    float* out   = (float*)d_out;
    float* s_out = out;                               // [4,8192,1536]
    float* w_out = out + (size_t)NB * NR * SD;        // [4,8192,32]

    p1_kernel<<<dim3(AD / 256, BS / 32, KS), 128>>>(sl, Wk);
    p1r_kernel<<<(BS * AD / 4) / 256, 256>>>();
    p2_kernel<<<dim3(192 / JT, AC), 256>>>(Wq);
    p2r_kernel<<<(IN_DIM * BS) / 256, 256>>>();
    c1_kernel<<<(NB * NR) / C1_ROWS, 256>>>(x, w_out);
    c2_kernel<<<dim3(SD / 128, (NB * NR) / 64), 128>>>(sl, w_out, s_out);
}